// round 15
// baseline (speedup 1.0000x reference)
#include <cuda_runtime.h>

#define NROI 1024
#define NB   8
#define FH   160
#define FW   160
#define CC   256
#define CROPN 14
#define PO   7

// Per-ROI params: {ybase, ystep, xbase, xstep}; batch packed into g_perm.
__device__ float4 g_rp[NROI];
__device__ int    g_perm[NROI];          // (roi << 4) | batch

// Light fused setup: per-ROI params + bucket sort by image id (one block).
__global__ __launch_bounds__(NROI) void roi_setup_kernel(
    const float* __restrict__ rois,
    const float* __restrict__ iminfo)
{
    __shared__ int cnt[NB];
    __shared__ int off[NB];
    const int i = threadIdx.x;

    const float rid = rois[i * 5 + 0];
    const float rx1 = rois[i * 5 + 1];
    const float ry1 = rois[i * 5 + 2];
    const float rx2 = rois[i * 5 + 3];
    const float ry2 = rois[i * 5 + 4];
    const float imh = iminfo[i * 2 + 0];
    const float imw = iminfo[i * 2 + 1];

    const float ybase = (ry1 / imh) * (float)(FH - 1);
    const float xbase = (rx1 / imw) * (float)(FW - 1);
    const float ystep = ((ry2 - ry1) / imh) * (float)(FH - 1) / (float)(CROPN - 1);
    const float xstep = ((rx2 - rx1) / imw) * (float)(FW - 1) / (float)(CROPN - 1);

    g_rp[i] = make_float4(ybase, ystep, xbase, xstep);

    if (i < NB) cnt[i] = 0;
    __syncthreads();
    const int b = (int)rid;
    atomicAdd(&cnt[b], 1);
    __syncthreads();
    if (i == 0) {
        int s = 0;
        for (int k = 0; k < NB; ++k) { off[k] = s; s += cnt[k]; }
    }
    __syncthreads();
    const int pos = atomicAdd(&off[b], 1);
    g_perm[pos] = (i << 4) | b;
}

// One block per (sorted-roi, pooled-row). 448 threads = 7 px * 64 lanes.
// Lane t owns channels {2t,2t+1,128+2t,128+2t+1} via LDG.64.
// Per dxi, ALL 16 tap loads (both y rows, both channel halves) are issued
// as one batch before any dependent math — max per-warp MLP.
__global__ __launch_bounds__(448, 3) void roi_pool_kernel(
    const float* __restrict__ img,
    float* __restrict__ out)
{
    const int blk = blockIdx.x;
    const int sr  = blk / PO;
    const int py  = blk - sr * PO;
    const int pk  = g_perm[sr];
    const int roi = pk >> 4;
    const int b   = pk & 15;
    const int px  = threadIdx.x >> 6;        // 0..6, warp-uniform
    const int t   = threadIdx.x & 63;

    const float4 rp = __ldg(&g_rp[roi]);
    const float ybase = rp.x, ystep = rp.y, xbase = rp.z, xstep = rp.w;

    const float2* imgb = (const float2*)(img + (size_t)b * (FH * FW * CC)) + t;

    // Y geometry for both rows of this pool window (block-uniform)
    const float y0  = fmaf((float)(2 * py),     ystep, ybase);
    const float y1  = fmaf((float)(2 * py + 1), ystep, ybase);
    const float vy0 = (y0 >= 0.0f && y0 <= (float)(FH - 1)) ? 1.0f : 0.0f;
    const float vy1 = (y1 >= 0.0f && y1 <= (float)(FH - 1)) ? 1.0f : 0.0f;
    const float yf0 = floorf(y0), yf1 = floorf(y1);
    const float wy0 = y0 - yf0,   wy1 = y1 - yf1;
    const int yl0 = (int)fminf(fmaxf(yf0,        0.0f), (float)(FH - 1));
    const int yh0 = (int)fminf(fmaxf(yf0 + 1.0f, 0.0f), (float)(FH - 1));
    const int yl1 = (int)fminf(fmaxf(yf1,        0.0f), (float)(FH - 1));
    const int yh1 = (int)fminf(fmaxf(yf1 + 1.0f, 0.0f), (float)(FH - 1));

    const float2* rl0 = imgb + yl0 * (FW * CC / 2);
    const float2* rh0 = imgb + yh0 * (FW * CC / 2);
    const float2* rl1 = imgb + yl1 * (FW * CC / 2);
    const float2* rh1 = imgb + yh1 * (FW * CC / 2);

    float best0 = -3.402823466e38f;
    float best1 = -3.402823466e38f;
    float best2 = -3.402823466e38f;
    float best3 = -3.402823466e38f;

    #pragma unroll
    for (int dxi = 0; dxi < 2; ++dxi) {
        const int   ix = 2 * px + dxi;
        const float x  = fmaf((float)ix, xstep, xbase);
        const float vx = (x >= 0.0f && x <= (float)(FW - 1)) ? 1.0f : 0.0f;
        const float xf = floorf(x);
        const float wx = x - xf;
        const int   xl = (int)fminf(fmaxf(xf,        0.0f), (float)(FW - 1)) * (CC / 2);
        const int   xh = (int)fminf(fmaxf(xf + 1.0f, 0.0f), (float)(FW - 1)) * (CC / 2);

        // ---- one 16-load batch: y0/y1 x tl/tr/bl/br x chanA/chanB ----
        const float2 tl0A = __ldg(rl0 + xl),      tl0B = __ldg(rl0 + xl + 64);
        const float2 tr0A = __ldg(rl0 + xh),      tr0B = __ldg(rl0 + xh + 64);
        const float2 bl0A = __ldg(rh0 + xl),      bl0B = __ldg(rh0 + xl + 64);
        const float2 br0A = __ldg(rh0 + xh),      br0B = __ldg(rh0 + xh + 64);
        const float2 tl1A = __ldg(rl1 + xl),      tl1B = __ldg(rl1 + xl + 64);
        const float2 tr1A = __ldg(rl1 + xh),      tr1B = __ldg(rl1 + xh + 64);
        const float2 bl1A = __ldg(rh1 + xl),      bl1B = __ldg(rh1 + xl + 64);
        const float2 br1A = __ldg(rh1 + xh),      br1B = __ldg(rh1 + xh + 64);

        const float vv0 = vy0 * vx;
        const float vv1 = vy1 * vx;

        float top, bot, v;

        // y0 sample
        top = fmaf(tr0A.x - tl0A.x, wx, tl0A.x);
        bot = fmaf(br0A.x - bl0A.x, wx, bl0A.x);
        v   = fmaf(bot - top, wy0, top) * vv0;   best0 = fmaxf(best0, v);
        top = fmaf(tr0A.y - tl0A.y, wx, tl0A.y);
        bot = fmaf(br0A.y - bl0A.y, wx, bl0A.y);
        v   = fmaf(bot - top, wy0, top) * vv0;   best1 = fmaxf(best1, v);
        top = fmaf(tr0B.x - tl0B.x, wx, tl0B.x);
        bot = fmaf(br0B.x - bl0B.x, wx, bl0B.x);
        v   = fmaf(bot - top, wy0, top) * vv0;   best2 = fmaxf(best2, v);
        top = fmaf(tr0B.y - tl0B.y, wx, tl0B.y);
        bot = fmaf(br0B.y - bl0B.y, wx, bl0B.y);
        v   = fmaf(bot - top, wy0, top) * vv0;   best3 = fmaxf(best3, v);

        // y1 sample
        top = fmaf(tr1A.x - tl1A.x, wx, tl1A.x);
        bot = fmaf(br1A.x - bl1A.x, wx, bl1A.x);
        v   = fmaf(bot - top, wy1, top) * vv1;   best0 = fmaxf(best0, v);
        top = fmaf(tr1A.y - tl1A.y, wx, tl1A.y);
        bot = fmaf(br1A.y - bl1A.y, wx, bl1A.y);
        v   = fmaf(bot - top, wy1, top) * vv1;   best1 = fmaxf(best1, v);
        top = fmaf(tr1B.x - tl1B.x, wx, tl1B.x);
        bot = fmaf(br1B.x - bl1B.x, wx, bl1B.x);
        v   = fmaf(bot - top, wy1, top) * vv1;   best2 = fmaxf(best2, v);
        top = fmaf(tr1B.y - tl1B.y, wx, tl1B.y);
        bot = fmaf(br1B.y - bl1B.y, wx, bl1B.y);
        v   = fmaf(bot - top, wy1, top) * vv1;   best3 = fmaxf(best3, v);
    }

    float2* o = (float2*)(out + ((size_t)(roi * PO + py) * PO + px) * CC) + t;
    float2 s0; s0.x = best0; s0.y = best1;
    float2 s1; s1.x = best2; s1.y = best3;
    o[0]  = s0;
    o[64] = s1;
}

extern "C" void kernel_launch(void* const* d_in, const int* in_sizes, int n_in,
                              void* d_out, int out_size)
{
    (void)in_sizes; (void)n_in; (void)out_size;
    const float* img    = (const float*)d_in[0];
    const float* rois   = (const float*)d_in[1];
    const float* iminfo = (const float*)d_in[2];
    float*       out    = (float*)d_out;

    roi_setup_kernel<<<1, NROI>>>(rois, iminfo);
    roi_pool_kernel<<<NROI * PO, 448>>>(img, out);
}